// round 1
// baseline (speedup 1.0000x reference)
#include <cuda_runtime.h>
#include <math.h>

#define Sx 512
#define Bx 256
#define Ix 256
#define Hx 1024
#define SWx 256
#define SDx 100
#define KTOT 1536        // I + SW + H
#define GRID 128
#define NTHR 256
#define KC 32
#define NCHUNK (KTOT / KC)   // 48

// ---------------- persistent device state ----------------
__device__ float g_c[(size_t)Bx * Hx];
__device__ float g_stack[2][(size_t)Bx * SDx * SWx];
__device__ float g_d[(size_t)Bx * SWx];
__device__ float g_ctl[Bx * 4];
__device__ unsigned g_bar_count = 0;
__device__ unsigned g_bar_gen = 0;

// ---------------- helpers ----------------
__device__ __forceinline__ float sigf(float x) { return 1.0f / (1.0f + expf(-x)); }

__device__ __forceinline__ unsigned f2tf(float x) {
    unsigned r;
    asm("cvt.rna.tf32.f32 %0, %1;" : "=r"(r) : "f"(x));
    return r;
}

__device__ __forceinline__ void mma_tf32(float* c, const unsigned* a, const unsigned* b) {
    asm volatile(
        "mma.sync.aligned.m16n8k8.row.col.f32.tf32.tf32.f32 "
        "{%0,%1,%2,%3},{%4,%5,%6,%7},{%8,%9},{%0,%1,%2,%3};"
        : "+f"(c[0]), "+f"(c[1]), "+f"(c[2]), "+f"(c[3])
        : "r"(a[0]), "r"(a[1]), "r"(a[2]), "r"(a[3]), "r"(b[0]), "r"(b[1]));
}

__device__ __forceinline__ void gridbar() {
    __syncthreads();
    if (threadIdx.x == 0) {
        __threadfence();
        unsigned old = atomicAdd(&g_bar_count, 1u);
        if ((old % GRID) == (GRID - 1u)) {
            atomicAdd(&g_bar_gen, 1u);
        } else {
            unsigned target = old / GRID + 1u;
            while ((int)(*(volatile unsigned*)&g_bar_gen - target) < 0) {
                __nanosleep(32);
            }
        }
        __threadfence();
    }
    __syncthreads();
}

// ---------------- shared memory (phase union) ----------------
struct SmemP1 { float A[128 * 36]; float W[64 * 36]; };
struct SmemP2 { float hs[64 * 33]; float dws[16 * 68]; };
union Smem {
    SmemP1 p1;
    float gates[128 * 68];
    SmemP2 p2;
};

__global__ void __launch_bounds__(NTHR)
stackrnn_kernel(const float* __restrict__ x, const float* __restrict__ h0,
                const float* __restrict__ c0, const float* __restrict__ stack0,
                const float* __restrict__ W_ih, const float* __restrict__ W_hh,
                const float* __restrict__ b_ih, const float* __restrict__ b_hh,
                const float* __restrict__ A_w, const float* __restrict__ A_b,
                const float* __restrict__ D_w, const float* __restrict__ D_b,
                float* __restrict__ out) {
    __shared__ Smem sm;
    const int tid = threadIdx.x;
    const int cta = blockIdx.x;

    float* outs = out;                                    // (S,B,H)
    float* out_hn = out + (size_t)Sx * Bx * Hx;           // (1,B,H)
    float* out_cn = out_hn + (size_t)Bx * Hx;             // (1,B,H)
    float* out_st = out_cn + (size_t)Bx * Hx;             // (B,SD,SW)

    // ---- P1 mapping: CTA tile = 128 batches x (16 hidden units * 4 gates) ----
    const int mt = cta & 1;          // M tile (batch half)
    const int nt = cta >> 1;         // 64 hidden-unit tiles
    const int u0 = nt * 16;
    const int row0 = mt * 128;
    const int warp = tid >> 5, lane = tid & 31;
    const int wm = warp & 3, wn = warp >> 2;       // 4x2 warp grid over 128x64
    const int gi = lane >> 2, tg = lane & 3;
    const int m_base = wm * 32, n_base = wn * 32;

    for (int t = 0; t < Sx; ++t) {
        const float* hprev = (t == 0) ? h0 : (outs + (size_t)(t - 1) * Bx * Hx);
        const float* stk_r = (t == 0) ? stack0 : g_stack[t & 1];

        // ======================= P1: gates GEMM + fused LSTM =======================
        float acc[2][4][4];
#pragma unroll
        for (int a = 0; a < 2; a++)
#pragma unroll
            for (int b = 0; b < 4; b++)
#pragma unroll
                for (int c = 0; c < 4; c++) acc[a][b][c] = 0.f;

        float4 aR[4];
        float4 wR[2];

        auto loadA = [&](int k0) {
#pragma unroll
            for (int ii = 0; ii < 4; ii++) {
                int e = tid + ii * NTHR;
                int arow = e >> 3, c4 = e & 7;
                int k = k0 + c4 * 4;
                int b = row0 + arow;
                const float* p;
                if (k0 < Ix)
                    p = x + (size_t)t * Bx * Ix + (size_t)b * Ix + k;
                else if (k0 < Ix + SWx)
                    p = stk_r + (size_t)b * SDx * SWx + (k - Ix);
                else
                    p = hprev + (size_t)b * Hx + (k - (Ix + SWx));
                aR[ii] = __ldcg((const float4*)p);
            }
        };
        auto loadW = [&](int k0) {
#pragma unroll
            for (int ii = 0; ii < 2; ii++) {
                int e = tid + ii * NTHR;
                int n = e >> 3, c4 = e & 7;
                int k = k0 + c4 * 4;
                int r = ((n >> 4) << 10) + u0 + (n & 15);
                const float* p = (k < Ix + SWx)
                                     ? (W_ih + (size_t)r * (Ix + SWx) + k)
                                     : (W_hh + (size_t)r * Hx + (k - (Ix + SWx)));
                wR[ii] = __ldg((const float4*)p);
            }
        };
        auto storeSm = [&]() {
#pragma unroll
            for (int ii = 0; ii < 4; ii++) {
                int e = tid + ii * NTHR;
                int arow = e >> 3, c4 = e & 7;
                float* d = &sm.p1.A[arow * 36 + c4 * 4];
                d[0] = __uint_as_float(f2tf(aR[ii].x));
                d[1] = __uint_as_float(f2tf(aR[ii].y));
                d[2] = __uint_as_float(f2tf(aR[ii].z));
                d[3] = __uint_as_float(f2tf(aR[ii].w));
            }
#pragma unroll
            for (int ii = 0; ii < 2; ii++) {
                int e = tid + ii * NTHR;
                int n = e >> 3, c4 = e & 7;
                float* d = &sm.p1.W[n * 36 + c4 * 4];
                d[0] = __uint_as_float(f2tf(wR[ii].x));
                d[1] = __uint_as_float(f2tf(wR[ii].y));
                d[2] = __uint_as_float(f2tf(wR[ii].z));
                d[3] = __uint_as_float(f2tf(wR[ii].w));
            }
        };

        loadA(0);
        loadW(0);
        for (int kc = 0; kc < NCHUNK; kc++) {
            __syncthreads();   // smem free (prev chunk's mma done)
            storeSm();
            __syncthreads();   // smem visible
            if (kc + 1 < NCHUNK) { loadA((kc + 1) * KC); loadW((kc + 1) * KC); }
#pragma unroll
            for (int kk = 0; kk < 4; kk++) {
                const int kb = kk * 8;
                unsigned afr[2][4], bfr[4][2];
#pragma unroll
                for (int mi = 0; mi < 2; mi++) {
                    int r0 = m_base + mi * 16 + gi;
                    afr[mi][0] = __float_as_uint(sm.p1.A[r0 * 36 + kb + tg]);
                    afr[mi][1] = __float_as_uint(sm.p1.A[(r0 + 8) * 36 + kb + tg]);
                    afr[mi][2] = __float_as_uint(sm.p1.A[r0 * 36 + kb + 4 + tg]);
                    afr[mi][3] = __float_as_uint(sm.p1.A[(r0 + 8) * 36 + kb + 4 + tg]);
                }
#pragma unroll
                for (int ni = 0; ni < 4; ni++) {
                    int c0i = n_base + ni * 8 + gi;
                    bfr[ni][0] = __float_as_uint(sm.p1.W[c0i * 36 + kb + tg]);
                    bfr[ni][1] = __float_as_uint(sm.p1.W[c0i * 36 + kb + 4 + tg]);
                }
#pragma unroll
                for (int mi = 0; mi < 2; mi++)
#pragma unroll
                    for (int ni = 0; ni < 4; ni++) mma_tf32(acc[mi][ni], afr[mi], bfr[ni]);
            }
        }
        __syncthreads();
        // stage gates tile (128 x 64) to smem
#pragma unroll
        for (int mi = 0; mi < 2; mi++)
#pragma unroll
            for (int ni = 0; ni < 4; ni++) {
                int row = m_base + mi * 16 + gi;
                int coln = n_base + ni * 8 + tg * 2;
                sm.gates[row * 68 + coln] = acc[mi][ni][0];
                sm.gates[row * 68 + coln + 1] = acc[mi][ni][1];
                sm.gates[(row + 8) * 68 + coln] = acc[mi][ni][2];
                sm.gates[(row + 8) * 68 + coln + 1] = acc[mi][ni][3];
            }
        __syncthreads();
        // fused LSTM pointwise
#pragma unroll
        for (int ii = 0; ii < 8; ii++) {
            int e = tid + ii * NTHR;
            int arow = e >> 4, up = e & 15;
            int u = u0 + up;
            int b = row0 + arow;
            float iv = sm.gates[arow * 68 + up] + b_ih[u] + b_hh[u];
            float fv = sm.gates[arow * 68 + 16 + up] + b_ih[Hx + u] + b_hh[Hx + u];
            float gv = sm.gates[arow * 68 + 32 + up] + b_ih[2 * Hx + u] + b_hh[2 * Hx + u];
            float ov = sm.gates[arow * 68 + 48 + up] + b_ih[3 * Hx + u] + b_hh[3 * Hx + u];
            float cold = (t == 0) ? c0[(size_t)b * Hx + u] : g_c[(size_t)b * Hx + u];
            float cnew = sigf(fv) * cold + sigf(iv) * tanhf(gv);
            float hnew = sigf(ov) * tanhf(cnew);
            g_c[(size_t)b * Hx + u] = cnew;
            outs[(size_t)t * Bx * Hx + (size_t)b * Hx + u] = hnew;
        }
        gridbar();

        // ======================= P2: D-GEMM + controls softmax =======================
        {
            const int mtile = cta >> 4;    // 8 tiles of 32 batches
            const int ntile = cta & 15;    // 16 tiles of 16 cols
            const float* ht = outs + (size_t)t * Bx * Hx;
            const int xr = tid & 31, yr = tid >> 5;
            float a0 = 0.f, a1 = 0.f;
            for (int kc2 = 0; kc2 < Hx; kc2 += 64) {
#pragma unroll
                for (int ii = 0; ii < 2; ii++) {
                    int e = tid + ii * NTHR;
                    int r = e >> 4, c4 = e & 15;
                    int k = c4 * 4;
                    float4 v = __ldcg((const float4*)(ht + (size_t)(mtile * 32 + r) * Hx + kc2 + k));
                    sm.p2.hs[(k + 0) * 33 + r] = v.x;
                    sm.p2.hs[(k + 1) * 33 + r] = v.y;
                    sm.p2.hs[(k + 2) * 33 + r] = v.z;
                    sm.p2.hs[(k + 3) * 33 + r] = v.w;
                }
                {
                    int r = tid >> 4, c4 = tid & 15;
                    float4 v = __ldg((const float4*)(D_w + (size_t)(ntile * 16 + r) * Hx + kc2 + c4 * 4));
                    float* dd = &sm.p2.dws[r * 68 + c4 * 4];
                    dd[0] = v.x; dd[1] = v.y; dd[2] = v.z; dd[3] = v.w;
                }
                __syncthreads();
#pragma unroll
                for (int k = 0; k < 64; k++) {
                    float hv = sm.p2.hs[k * 33 + xr];
                    a0 += hv * sm.p2.dws[yr * 68 + k];
                    a1 += hv * sm.p2.dws[(yr + 8) * 68 + k];
                }
                __syncthreads();
            }
            int b = mtile * 32 + xr;
            int j0 = ntile * 16 + yr, j1 = j0 + 8;
            g_d[(size_t)b * SWx + j0] = tanhf(a0 + D_b[j0]);
            g_d[(size_t)b * SWx + j1] = tanhf(a1 + D_b[j1]);

            if (cta < 32) {   // controls: warp per batch
                int b2 = cta * 8 + warp;
                const float* hb = ht + (size_t)b2 * Hx;
                float s0 = 0.f, s1 = 0.f, s2 = 0.f;
                for (int k = lane; k < Hx; k += 32) {
                    float hv = __ldcg(hb + k);
                    s0 += hv * A_w[k];
                    s1 += hv * A_w[Hx + k];
                    s2 += hv * A_w[2 * Hx + k];
                }
#pragma unroll
                for (int o = 16; o > 0; o >>= 1) {
                    s0 += __shfl_xor_sync(0xffffffffu, s0, o);
                    s1 += __shfl_xor_sync(0xffffffffu, s1, o);
                    s2 += __shfl_xor_sync(0xffffffffu, s2, o);
                }
                if (lane == 0) {
                    s0 += A_b[0]; s1 += A_b[1]; s2 += A_b[2];
                    float mx = fmaxf(s0, fmaxf(s1, s2));
                    float e0 = expf(s0 - mx), e1 = expf(s1 - mx), e2 = expf(s2 - mx);
                    float inv = 1.f / (e0 + e1 + e2);
                    g_ctl[b2 * 4 + 0] = e0 * inv;
                    g_ctl[b2 * 4 + 1] = e1 * inv;
                    g_ctl[b2 * 4 + 2] = e2 * inv;
                }
            }
        }
        gridbar();

        // ======================= P3: stack blend (+ final copies) =======================
        {
            float* wst = (t == Sx - 1) ? out_st : g_stack[(t + 1) & 1];
#pragma unroll
            for (int bi = 0; bi < 2; bi++) {
                int b = cta * 2 + bi;
                float push = __ldcg(&g_ctl[b * 4 + 0]);
                float pop = __ldcg(&g_ctl[b * 4 + 1]);
                float noop = __ldcg(&g_ctl[b * 4 + 2]);
                float dv = __ldcg(&g_d[(size_t)b * SWx + tid]);
                const float* sp = stk_r + (size_t)b * SDx * SWx + tid;
                float* dp = wst + (size_t)b * SDx * SWx + tid;
                float prev = dv;
                float cur = __ldcg(sp);
#pragma unroll 5
                for (int i = 0; i < SDx; i++) {
                    float nxt = (i < SDx - 1) ? __ldcg(sp + (size_t)(i + 1) * SWx) : 0.f;
                    dp[(size_t)i * SWx] = noop * cur + push * prev + pop * nxt;
                    prev = cur;
                    cur = nxt;
                }
            }
            if (t == Sx - 1) {
                const float* hlast = outs + (size_t)(Sx - 1) * Bx * Hx;
                for (int idx = cta * NTHR + tid; idx < Bx * Hx; idx += GRID * NTHR) {
                    out_hn[idx] = __ldcg(hlast + idx);
                    out_cn[idx] = __ldcg(&g_c[idx]);
                }
            }
        }
        gridbar();
    }
}

extern "C" void kernel_launch(void* const* d_in, const int* in_sizes, int n_in,
                              void* d_out, int out_size) {
    (void)in_sizes; (void)n_in; (void)out_size;
    stackrnn_kernel<<<GRID, NTHR>>>(
        (const float*)d_in[0], (const float*)d_in[1], (const float*)d_in[2],
        (const float*)d_in[3], (const float*)d_in[4], (const float*)d_in[5],
        (const float*)d_in[6], (const float*)d_in[7], (const float*)d_in[8],
        (const float*)d_in[9], (const float*)d_in[10], (const float*)d_in[11],
        (float*)d_out);
}